// round 2
// baseline (speedup 1.0000x reference)
#include <cuda_runtime.h>

typedef unsigned long long ull;

// ---------------- packed f32x2 helpers (Blackwell) ----------------
__device__ __forceinline__ ull ffma2(ull a, ull b, ull c) {
    ull d;
    asm("fma.rn.f32x2 %0, %1, %2, %3;" : "=l"(d) : "l"(a), "l"(b), "l"(c));
    return d;
}
__device__ __forceinline__ ull fadd2(ull a, ull b) {
    ull d;
    asm("add.rn.f32x2 %0, %1, %2;" : "=l"(d) : "l"(a), "l"(b));
    return d;
}
__device__ __forceinline__ ull pack2(float lo, float hi) {
    ull d;
    asm("mov.b64 %0, {%1, %2};" : "=l"(d) : "f"(lo), "f"(hi));
    return d;
}
__device__ __forceinline__ void unpack2(ull v, float& lo, float& hi) {
    asm("mov.b64 {%0, %1}, %2;" : "=f"(lo), "=f"(hi) : "l"(v));
}
__device__ __forceinline__ ull relu2(ull v) {
    float lo, hi;
    unpack2(v, lo, hi);
    return pack2(fmaxf(lo, 0.0f), fmaxf(hi, 0.0f));
}

// ---------------- quantized-weight scratch (device globals; no allocs) ----------------
// Duplicated layouts: each weight stored twice consecutively so a 64-bit load
// yields the (w, w) pair needed as an f32x2 operand shared by both packed rows.
__device__ __align__(16) float g_w1d[64 * 32];   // [j][2i]   : W1q row j, dup
__device__ __align__(16) float g_w2t[64 * 64];   // [j][2k]   : W2q^T col j, dup
__device__ __align__(16) float g_w3t[32 * 64];   // [j][2k]   : W3q^T col j, dup
__device__ __align__(16) float g_w4t[32 * 16];   // [j][2m]   : W4q^T col j, dup (m<5)
__device__ __align__(16) float g_b1d[128];
__device__ __align__(16) float g_b2d[64];
__device__ __align__(16) float g_b3d[64];
__device__ __align__(16) float g_b4d[16];

// ---------------- weight quantization (HAWQ, exact) ----------------
// per-output-channel: ws = max|W|/127 ; w_int = clip(round(W/ws), -127, 127) ; Wq = w_int*ws
// rintf = round-half-to-even == jnp.round ; __fdiv_rn = IEEE divide (immune to fast-math)
__global__ void prep_kernel(const float* __restrict__ W1, const float* __restrict__ b1,
                            const float* __restrict__ W2, const float* __restrict__ b2,
                            const float* __restrict__ W3, const float* __restrict__ b3,
                            const float* __restrict__ W4, const float* __restrict__ b4)
{
    int t = threadIdx.x;

    if (t < 64) {
        // W1 row t : 16 inputs
        float m = 0.0f;
        #pragma unroll
        for (int i = 0; i < 16; i++) m = fmaxf(m, fabsf(W1[t * 16 + i]));
        float ws = __fdiv_rn(m, 127.0f);
        #pragma unroll
        for (int i = 0; i < 16; i++) {
            float q = rintf(__fdiv_rn(W1[t * 16 + i], ws));
            q = fminf(fmaxf(q, -127.0f), 127.0f);
            float wq = q * ws;
            g_w1d[t * 32 + 2 * i]     = wq;
            g_w1d[t * 32 + 2 * i + 1] = wq;
        }
        g_b1d[2 * t]     = b1[t];
        g_b1d[2 * t + 1] = b1[t];
    } else if (t < 96) {
        int k = t - 64;  // W2 row k : 64 inputs
        float m = 0.0f;
        #pragma unroll
        for (int j = 0; j < 64; j++) m = fmaxf(m, fabsf(W2[k * 64 + j]));
        float ws = __fdiv_rn(m, 127.0f);
        #pragma unroll
        for (int j = 0; j < 64; j++) {
            float q = rintf(__fdiv_rn(W2[k * 64 + j], ws));
            q = fminf(fmaxf(q, -127.0f), 127.0f);
            float wq = q * ws;
            g_w2t[j * 64 + 2 * k]     = wq;
            g_w2t[j * 64 + 2 * k + 1] = wq;
        }
        g_b2d[2 * k]     = b2[k];
        g_b2d[2 * k + 1] = b2[k];
    } else if (t < 128) {
        int k = t - 96;  // W3 row k : 32 inputs
        float m = 0.0f;
        #pragma unroll
        for (int j = 0; j < 32; j++) m = fmaxf(m, fabsf(W3[k * 32 + j]));
        float ws = __fdiv_rn(m, 127.0f);
        #pragma unroll
        for (int j = 0; j < 32; j++) {
            float q = rintf(__fdiv_rn(W3[k * 32 + j], ws));
            q = fminf(fmaxf(q, -127.0f), 127.0f);
            float wq = q * ws;
            g_w3t[j * 64 + 2 * k]     = wq;
            g_w3t[j * 64 + 2 * k + 1] = wq;
        }
        g_b3d[2 * k]     = b3[k];
        g_b3d[2 * k + 1] = b3[k];
    }

    if (t < 5) {
        // W4 row t : 32 inputs (these threads also did W1 above; independent arrays)
        float m = 0.0f;
        #pragma unroll
        for (int j = 0; j < 32; j++) m = fmaxf(m, fabsf(W4[t * 32 + j]));
        float ws = __fdiv_rn(m, 127.0f);
        #pragma unroll
        for (int j = 0; j < 32; j++) {
            float q = rintf(__fdiv_rn(W4[t * 32 + j], ws));
            q = fminf(fmaxf(q, -127.0f), 127.0f);
            float wq = q * ws;
            g_w4t[j * 16 + 2 * t]     = wq;
            g_w4t[j * 16 + 2 * t + 1] = wq;
        }
        g_b4d[2 * t]     = b4[t];
        g_b4d[2 * t + 1] = b4[t];
    }
    if (t >= 5 && t < 8) {
        g_b4d[2 * t]     = 0.0f;
        g_b4d[2 * t + 1] = 0.0f;
    }
}

// ---------------- fused MLP: 2 rows per thread via f32x2 ----------------
__global__ __launch_bounds__(128)
void mlp_kernel(const float* __restrict__ x, float* __restrict__ out, int B)
{
    __shared__ __align__(16) float s_w1[64 * 32];
    __shared__ __align__(16) float s_w2[64 * 64];
    __shared__ __align__(16) float s_w3[32 * 64];
    __shared__ __align__(16) float s_w4[32 * 16];
    __shared__ __align__(16) float s_b1[128];
    __shared__ __align__(16) float s_b2[64];
    __shared__ __align__(16) float s_b3[64];
    __shared__ __align__(16) float s_b4[16];

    int t = threadIdx.x;
    for (int i = t; i < 64 * 32; i += 128) s_w1[i] = g_w1d[i];
    for (int i = t; i < 64 * 64; i += 128) s_w2[i] = g_w2t[i];
    for (int i = t; i < 32 * 64; i += 128) s_w3[i] = g_w3t[i];
    for (int i = t; i < 32 * 16; i += 128) s_w4[i] = g_w4t[i];
    s_b1[t] = g_b1d[t];
    if (t < 64) { s_b2[t] = g_b2d[t]; s_b3[t] = g_b3d[t]; }
    if (t < 16) s_b4[t] = g_b4d[t];
    __syncthreads();

    int tid = blockIdx.x * 128 + t;        // rows 2*tid, 2*tid+1
    if (2 * tid + 1 >= B) return;          // B is even; guard is defensive

    // Load both input rows (16 floats each) and pack lane-wise: (rowA_i, rowB_i)
    const float4* xin = (const float4*)(x + (size_t)tid * 32);
    float xa[16], xb[16];
    *(float4*)&xa[0]  = xin[0];
    *(float4*)&xa[4]  = xin[1];
    *(float4*)&xa[8]  = xin[2];
    *(float4*)&xa[12] = xin[3];
    *(float4*)&xb[0]  = xin[4];
    *(float4*)&xb[4]  = xin[5];
    *(float4*)&xb[8]  = xin[6];
    *(float4*)&xb[12] = xin[7];
    ull xp[16];
    #pragma unroll
    for (int i = 0; i < 16; i++) xp[i] = pack2(xa[i], xb[i]);

    // ---- Layer1 (16->64) streamed into Layer2 (64->32) accumulators ----
    ull h2[32];
    #pragma unroll
    for (int k = 0; k < 32; k++) h2[k] = *(const ull*)&s_b2[2 * k];

    #pragma unroll 8
    for (int j = 0; j < 64; j++) {
        const ull* w1row = (const ull*)&s_w1[j * 32];
        ull acc0 = *(const ull*)&s_b1[2 * j];
        ull acc1 = pack2(0.0f, 0.0f);
        #pragma unroll
        for (int i = 0; i < 16; i += 2) {
            acc0 = ffma2(xp[i],     w1row[i],     acc0);
            acc1 = ffma2(xp[i + 1], w1row[i + 1], acc1);
        }
        ull h1 = relu2(fadd2(acc0, acc1));
        const ull* w2col = (const ull*)&s_w2[j * 64];
        #pragma unroll
        for (int k = 0; k < 32; k++) h2[k] = ffma2(h1, w2col[k], h2[k]);
    }

    // ---- Layer3 (32->32), consuming relu(h2) ----
    ull h3[32];
    #pragma unroll
    for (int k = 0; k < 32; k++) h3[k] = *(const ull*)&s_b3[2 * k];

    #pragma unroll 8
    for (int j = 0; j < 32; j++) {
        ull a = relu2(h2[j]);
        const ull* w3col = (const ull*)&s_w3[j * 64];
        #pragma unroll
        for (int k = 0; k < 32; k++) h3[k] = ffma2(a, w3col[k], h3[k]);
    }

    // ---- Layer4 (32->5), consuming relu(h3) ----
    ull o[5];
    #pragma unroll
    for (int m = 0; m < 5; m++) o[m] = *(const ull*)&s_b4[2 * m];

    #pragma unroll 8
    for (int j = 0; j < 32; j++) {
        ull a = relu2(h3[j]);
        const ull* w4 = (const ull*)&s_w4[j * 16];
        #pragma unroll
        for (int m = 0; m < 5; m++) o[m] = ffma2(a, w4[m], o[m]);
    }

    // ---- softmax per row ----
    float la[5], lb[5];
    #pragma unroll
    for (int m = 0; m < 5; m++) unpack2(o[m], la[m], lb[m]);

    float mA = la[0], mB = lb[0];
    #pragma unroll
    for (int m = 1; m < 5; m++) { mA = fmaxf(mA, la[m]); mB = fmaxf(mB, lb[m]); }
    float sA = 0.0f, sB = 0.0f;
    #pragma unroll
    for (int m = 0; m < 5; m++) {
        la[m] = expf(la[m] - mA); sA += la[m];
        lb[m] = expf(lb[m] - mB); sB += lb[m];
    }
    float rA = __fdiv_rn(1.0f, sA);
    float rB = __fdiv_rn(1.0f, sB);

    float* outA = out + (size_t)(2 * tid) * 5;
    #pragma unroll
    for (int m = 0; m < 5; m++) outA[m]     = la[m] * rA;
    #pragma unroll
    for (int m = 0; m < 5; m++) outA[5 + m] = lb[m] * rB;
}

// ---------------- launch ----------------
extern "C" void kernel_launch(void* const* d_in, const int* in_sizes, int n_in,
                              void* d_out, int out_size)
{
    const float* x  = (const float*)d_in[0];
    const float* W1 = (const float*)d_in[1];
    const float* b1 = (const float*)d_in[2];
    const float* W2 = (const float*)d_in[3];
    const float* b2 = (const float*)d_in[4];
    const float* W3 = (const float*)d_in[5];
    const float* b3 = (const float*)d_in[6];
    const float* W4 = (const float*)d_in[7];
    const float* b4 = (const float*)d_in[8];

    int B = in_sizes[0] / 16;

    prep_kernel<<<1, 128>>>(W1, b1, W2, b2, W3, b3, W4, b4);

    int threads = (B + 1) / 2;                  // one thread per 2 rows
    int blocks  = (threads + 127) / 128;
    mlp_kernel<<<blocks, 128>>>(x, (float*)d_out, B);
}

// round 4
// speedup vs baseline: 2.1819x; 2.1819x over previous
#include <cuda_runtime.h>

typedef unsigned long long ull;

// ---------------- packed f32x2 helpers (Blackwell) ----------------
__device__ __forceinline__ ull ffma2(ull a, ull b, ull c) {
    ull d;
    asm("fma.rn.f32x2 %0, %1, %2, %3;" : "=l"(d) : "l"(a), "l"(b), "l"(c));
    return d;
}
__device__ __forceinline__ ull fadd2(ull a, ull b) {
    ull d;
    asm("add.rn.f32x2 %0, %1, %2;" : "=l"(d) : "l"(a), "l"(b));
    return d;
}
__device__ __forceinline__ ull pack2(float lo, float hi) {
    ull d;
    asm("mov.b64 %0, {%1, %2};" : "=l"(d) : "f"(lo), "f"(hi));
    return d;
}
__device__ __forceinline__ void unpack2(ull v, float& lo, float& hi) {
    asm("mov.b64 {%0, %1}, %2;" : "=f"(lo), "=f"(hi) : "l"(v));
}
__device__ __forceinline__ ull relu2(ull v) {
    float lo, hi;
    unpack2(v, lo, hi);
    return pack2(fmaxf(lo, 0.0f), fmaxf(hi, 0.0f));
}

// ---------------- quantized-weight scratch (device globals) ----------------
// Channel-pair layouts (NO duplication):
//   g_w1p[j2][..]  pair = (W1q[2j2][i], W1q[2j2+1][i]) at float offset j2*32+2i+b
//   g_w2p[j][k]    = W2q[k][j] (transpose; pair k2 = (2k2, 2k2+1))
//   g_w3 [k][j]    = W3q[k][j] natural rows (pairs match h2 channel pairs)
//   g_w4p[k][m]    = W4q[m][k], m<5, padded to 8
__device__ __align__(16) float g_w1p[32 * 32];
__device__ __align__(16) float g_w2p[64 * 32];
__device__ __align__(16) float g_w3 [32 * 32];
__device__ __align__(16) float g_w4p[32 * 8];
__device__ __align__(16) float g_b1[64];
__device__ __align__(16) float g_b2[32];
__device__ __align__(16) float g_b3[32];
__device__ __align__(16) float g_b4p[8];

// ---------------- weight quantization (HAWQ, exact) ----------------
// per-output-channel: ws = max|W|/127 ; w_int = clip(round(W/ws)) ; Wq = w_int*ws
// rintf = round-half-even == jnp.round ; __fdiv_rn = IEEE divide (fast-math-proof)
__global__ void prep_kernel(const float* __restrict__ W1, const float* __restrict__ b1,
                            const float* __restrict__ W2, const float* __restrict__ b2,
                            const float* __restrict__ W3, const float* __restrict__ b3,
                            const float* __restrict__ W4, const float* __restrict__ b4)
{
    int t = threadIdx.x;

    if (t < 64) {
        // W1 row t : 16 inputs -> interleaved pair layout
        float m = 0.0f;
        #pragma unroll
        for (int i = 0; i < 16; i++) m = fmaxf(m, fabsf(W1[t * 16 + i]));
        float ws = __fdiv_rn(m, 127.0f);
        #pragma unroll
        for (int i = 0; i < 16; i++) {
            float q = rintf(__fdiv_rn(W1[t * 16 + i], ws));
            q = fminf(fmaxf(q, -127.0f), 127.0f);
            g_w1p[(t >> 1) * 32 + 2 * i + (t & 1)] = q * ws;
        }
        g_b1[t] = b1[t];
    } else if (t < 96) {
        int k = t - 64;  // W2 row k : 64 inputs -> transpose
        float m = 0.0f;
        #pragma unroll
        for (int j = 0; j < 64; j++) m = fmaxf(m, fabsf(W2[k * 64 + j]));
        float ws = __fdiv_rn(m, 127.0f);
        #pragma unroll
        for (int j = 0; j < 64; j++) {
            float q = rintf(__fdiv_rn(W2[k * 64 + j], ws));
            q = fminf(fmaxf(q, -127.0f), 127.0f);
            g_w2p[j * 32 + k] = q * ws;
        }
        g_b2[k] = b2[k];
    } else if (t < 128) {
        int k = t - 96;  // W3 row k : 32 inputs -> natural
        float m = 0.0f;
        #pragma unroll
        for (int j = 0; j < 32; j++) m = fmaxf(m, fabsf(W3[k * 32 + j]));
        float ws = __fdiv_rn(m, 127.0f);
        #pragma unroll
        for (int j = 0; j < 32; j++) {
            float q = rintf(__fdiv_rn(W3[k * 32 + j], ws));
            q = fminf(fmaxf(q, -127.0f), 127.0f);
            g_w3[k * 32 + j] = q * ws;
        }
        g_b3[k] = b3[k];
    }

    if (t < 5) {
        // W4 row t : 32 inputs -> transposed+padded (independent arrays from W1 work)
        float m = 0.0f;
        #pragma unroll
        for (int j = 0; j < 32; j++) m = fmaxf(m, fabsf(W4[t * 32 + j]));
        float ws = __fdiv_rn(m, 127.0f);
        #pragma unroll
        for (int j = 0; j < 32; j++) {
            float q = rintf(__fdiv_rn(W4[t * 32 + j], ws));
            q = fminf(fmaxf(q, -127.0f), 127.0f);
            g_w4p[j * 8 + t] = q * ws;
        }
        g_b4p[t] = b4[t];
    }
    if (t >= 5 && t < 8) g_b4p[t] = 0.0f;
    if (t >= 8 && t < 11) {
        // pad columns 5,6,7 ONLY (t=8,9,10). (t<16 previously stomped real
        // W4 columns of the next row + wrote OOB -> 0.29 rel_err.)
        int c = (t - 8) + 5;
        #pragma unroll
        for (int j = 0; j < 32; j++) g_w4p[j * 8 + c] = 0.0f;
    }
}

// ---------------- fused MLP: 3 rows/thread, f32x2 packed over channels ----------------
__global__ __launch_bounds__(128, 2)
void mlp_kernel(const float* __restrict__ x, float* __restrict__ out, int B)
{
    __shared__ __align__(16) float s_w1p[32 * 32];
    __shared__ __align__(16) float s_w2p[64 * 32];
    __shared__ __align__(16) float s_w3 [32 * 32];
    __shared__ __align__(16) float s_w4p[32 * 8];
    __shared__ __align__(16) float s_b1[64];
    __shared__ __align__(16) float s_b2[32];
    __shared__ __align__(16) float s_b3[32];
    __shared__ __align__(16) float s_b4p[8];

    int t = threadIdx.x;
    for (int i = t; i < 32 * 32; i += 128) { s_w1p[i] = g_w1p[i]; s_w3[i] = g_w3[i]; }
    for (int i = t; i < 64 * 32; i += 128) s_w2p[i] = g_w2p[i];
    for (int i = t; i < 32 * 8;  i += 128) s_w4p[i] = g_w4p[i];
    if (t < 64) s_b1[t] = g_b1[t];
    else if (t < 96)  s_b2[t - 64] = g_b2[t - 64];
    else              s_b3[t - 96] = g_b3[t - 96];
    if (t < 8) s_b4p[t] = g_b4p[t];
    __syncthreads();

    long tid = (long)blockIdx.x * 128 + t;
    long r0 = tid * 3;
    if (r0 >= B) return;
    int nr = (int)((B - r0 >= 3) ? 3 : (B - r0));

    // ---- load 3 input rows, build duplicated pairs (x_i, x_i) ----
    ull xd[3][16];
    #pragma unroll
    for (int r = 0; r < 3; r++) {
        if (r < nr) {
            const float4* xr = (const float4*)(x + (size_t)(r0 + r) * 16);
            float4 a = xr[0], b = xr[1], c = xr[2], d = xr[3];
            xd[r][0]  = pack2(a.x, a.x); xd[r][1]  = pack2(a.y, a.y);
            xd[r][2]  = pack2(a.z, a.z); xd[r][3]  = pack2(a.w, a.w);
            xd[r][4]  = pack2(b.x, b.x); xd[r][5]  = pack2(b.y, b.y);
            xd[r][6]  = pack2(b.z, b.z); xd[r][7]  = pack2(b.w, b.w);
            xd[r][8]  = pack2(c.x, c.x); xd[r][9]  = pack2(c.y, c.y);
            xd[r][10] = pack2(c.z, c.z); xd[r][11] = pack2(c.w, c.w);
            xd[r][12] = pack2(d.x, d.x); xd[r][13] = pack2(d.y, d.y);
            xd[r][14] = pack2(d.z, d.z); xd[r][15] = pack2(d.w, d.w);
        } else {
            #pragma unroll
            for (int i = 0; i < 16; i++) xd[r][i] = 0ull;
        }
    }

    // ---- Phase A: L1 (16->64) streamed into L2 (64->32) ----
    // h2[r][k2] accumulates output-channel pair (2k2, 2k2+1) for row r.
    ull h2[3][16];
    #pragma unroll
    for (int k2 = 0; k2 < 16; k2++) {
        ull b2p = *(const ull*)&s_b2[2 * k2];
        h2[0][k2] = b2p; h2[1][k2] = b2p; h2[2][k2] = b2p;
    }

    #pragma unroll 4
    for (int j2 = 0; j2 < 32; j2++) {
        // L1: hidden-channel pair (2j2, 2j2+1) for all 3 rows
        ull bb = *(const ull*)&s_b1[2 * j2];
        ull acc0[3], acc1[3];
        #pragma unroll
        for (int r = 0; r < 3; r++) { acc0[r] = bb; acc1[r] = 0ull; }
        const ulonglong2* w1r = (const ulonglong2*)(s_w1p + j2 * 32);
        #pragma unroll
        for (int i2 = 0; i2 < 8; i2++) {
            ulonglong2 w = w1r[i2];
            #pragma unroll
            for (int r = 0; r < 3; r++) {
                acc0[r] = ffma2(xd[r][2 * i2],     w.x, acc0[r]);
                acc1[r] = ffma2(xd[r][2 * i2 + 1], w.y, acc1[r]);
            }
        }
        ull a0d[3], a1d[3];
        #pragma unroll
        for (int r = 0; r < 3; r++) {
            ull h = relu2(fadd2(acc0[r], acc1[r]));
            float u, v; unpack2(h, u, v);
            a0d[r] = pack2(u, u);
            a1d[r] = pack2(v, v);
        }
        // L2: scatter both hidden channels into all 16 output-channel pairs
        const ulonglong2* w2a = (const ulonglong2*)(s_w2p + (2 * j2) * 32);
        const ulonglong2* w2b = (const ulonglong2*)(s_w2p + (2 * j2 + 1) * 32);
        #pragma unroll
        for (int q = 0; q < 8; q++) {
            ulonglong2 wa = w2a[q];
            ulonglong2 wb = w2b[q];
            #pragma unroll
            for (int r = 0; r < 3; r++) {
                h2[r][2 * q]     = ffma2(a1d[r], wb.x, ffma2(a0d[r], wa.x, h2[r][2 * q]));
                h2[r][2 * q + 1] = ffma2(a1d[r], wb.y, ffma2(a0d[r], wa.y, h2[r][2 * q + 1]));
            }
        }
    }

    // ---- Phase B: relu(h2); L3 (32->32) streamed into L4 (32->5) ----
    #pragma unroll
    for (int k2 = 0; k2 < 16; k2++) {
        h2[0][k2] = relu2(h2[0][k2]);
        h2[1][k2] = relu2(h2[1][k2]);
        h2[2][k2] = relu2(h2[2][k2]);
    }

    ull o[3][3];
    {
        ull b4x = *(const ull*)&s_b4p[0];
        ull b4y = *(const ull*)&s_b4p[2];
        ull b4z = *(const ull*)&s_b4p[4];
        #pragma unroll
        for (int r = 0; r < 3; r++) { o[r][0] = b4x; o[r][1] = b4y; o[r][2] = b4z; }
    }

    #pragma unroll 4
    for (int k = 0; k < 32; k++) {
        const ulonglong2* w3r = (const ulonglong2*)(s_w3 + k * 32);
        ull d0[3] = {0ull, 0ull, 0ull}, d1[3] = {0ull, 0ull, 0ull};
        #pragma unroll
        for (int p = 0; p < 8; p++) {
            ulonglong2 w = w3r[p];
            #pragma unroll
            for (int r = 0; r < 3; r++) {
                d0[r] = ffma2(h2[r][2 * p],     w.x, d0[r]);
                d1[r] = ffma2(h2[r][2 * p + 1], w.y, d1[r]);
            }
        }
        float bk = s_b3[k];
        ulonglong2 w4xy = *(const ulonglong2*)(s_w4p + k * 8);
        ull w4z = *(const ull*)(s_w4p + k * 8 + 4);
        #pragma unroll
        for (int r = 0; r < 3; r++) {
            ull s2 = fadd2(d0[r], d1[r]);
            float u, v; unpack2(s2, u, v);
            float a = fmaxf(u + v + bk, 0.0f);
            ull ad = pack2(a, a);
            o[r][0] = ffma2(ad, w4xy.x, o[r][0]);
            o[r][1] = ffma2(ad, w4xy.y, o[r][1]);
            o[r][2] = ffma2(ad, w4z,    o[r][2]);
        }
    }

    // ---- softmax + store per valid row ----
    #pragma unroll
    for (int r = 0; r < 3; r++) {
        if (r >= nr) break;
        float l[6];
        unpack2(o[r][0], l[0], l[1]);
        unpack2(o[r][1], l[2], l[3]);
        unpack2(o[r][2], l[4], l[5]);
        float m = l[0];
        #pragma unroll
        for (int i = 1; i < 5; i++) m = fmaxf(m, l[i]);
        float s = 0.0f;
        #pragma unroll
        for (int i = 0; i < 5; i++) { l[i] = expf(l[i] - m); s += l[i]; }
        float inv = __fdiv_rn(1.0f, s);
        float* po = out + (size_t)(r0 + r) * 5;
        #pragma unroll
        for (int i = 0; i < 5; i++) po[i] = l[i] * inv;
    }
}

// ---------------- launch ----------------
extern "C" void kernel_launch(void* const* d_in, const int* in_sizes, int n_in,
                              void* d_out, int out_size)
{
    const float* x  = (const float*)d_in[0];
    const float* W1 = (const float*)d_in[1];
    const float* b1 = (const float*)d_in[2];
    const float* W2 = (const float*)d_in[3];
    const float* b2 = (const float*)d_in[4];
    const float* W3 = (const float*)d_in[5];
    const float* b3 = (const float*)d_in[6];
    const float* W4 = (const float*)d_in[7];
    const float* b4 = (const float*)d_in[8];

    int B = in_sizes[0] / 16;

    prep_kernel<<<1, 128>>>(W1, b1, W2, b2, W3, b3, W4, b4);

    long threads = ((long)B + 2) / 3;             // 3 rows per thread
    int blocks = (int)((threads + 127) / 128);
    mlp_kernel<<<blocks, 128>>>(x, (float*)d_out, B);
}